// round 15
// baseline (speedup 1.0000x reference)
#include <cuda_runtime.h>
#include <cuda_fp16.h>
#include <math.h>
#include <stdint.h>
#include <string.h>

#define N_USER 100000
#define N_ITEM 100000
#define NNODE  200000
#define E_HALF 600000
#define E_TOT  1200000
#define HID 128

// ------------------------- scratch (device globals, no alloc) ----------------
__device__ __half g_hw16[(size_t)NNODE * HID];   // proj output (gather source, layer 1)
__device__ __half g_h16[(size_t)NNODE * HID];    // fused agg+GEMM output (layer 2 pre-agg)
__device__ float  g_dinv[NNODE];
__device__ int    g_deg[NNODE];
__device__ int    g_rowptr[NNODE + 1];
__device__ int    g_cursor[NNODE];
__device__ int    g_col[E_TOT];
__device__ int    g_bsums[256];
__device__ float  g_bfold[2][HID];               // b_in @ W1 per node type

// fp16 weights, transposed Wt[n][k]
#define WT_WU 0
#define WT_WI 32768
#define WT_W2 65536
__device__ __half g_wt[81920];

// ------------------------- helpers -------------------------------------------
__device__ __forceinline__ uint32_t smem_u32(const void* p) {
    uint32_t a;
    asm("{ .reg .u64 t; cvta.to.shared.u64 t, %1; cvt.u32.u64 %0, t; }" : "=r"(a) : "l"(p));
    return a;
}

__device__ __forceinline__ uint32_t h2_as_u32(__half2 h) {
    uint32_t u;
    memcpy(&u, &h, 4);
    return u;
}

__device__ __forceinline__ void ldsm_x4(uint32_t& r0, uint32_t& r1,
                                        uint32_t& r2, uint32_t& r3, uint32_t addr) {
    asm volatile("ldmatrix.sync.aligned.m8n8.x4.shared.b16 {%0,%1,%2,%3}, [%4];"
                 : "=r"(r0), "=r"(r1), "=r"(r2), "=r"(r3) : "r"(addr));
}

__device__ __forceinline__ void mma16816(float* c, const uint32_t* a, const uint32_t* b) {
    asm volatile("mma.sync.aligned.m16n8k16.row.col.f32.f16.f16.f32 "
                 "{%0,%1,%2,%3}, {%4,%5,%6,%7}, {%8,%9}, {%0,%1,%2,%3};"
                 : "+f"(c[0]), "+f"(c[1]), "+f"(c[2]), "+f"(c[3])
                 : "r"(a[0]), "r"(a[1]), "r"(a[2]), "r"(a[3]), "r"(b[0]), "r"(b[1]));
}

// constants shared by GEMM kernels
#define WSTRIDE 272
#define WBYTES  (128 * WSTRIDE)
#define ASTRIDE 80
#define ABYTES  (128 * ASTRIDE)

// ------------------------- fused prep -----------------------------------------
__global__ void prep_all(const float* __restrict__ Wu, const float* __restrict__ Wi,
                         const float* __restrict__ W1, const float* __restrict__ W2,
                         const float* __restrict__ bu, const float* __restrict__ bi) {
    int blk = blockIdx.x, tid = threadIdx.x;
    if (blk < 256) {
        int i = blk * 256 + tid;
        int type = i >> 15;
        int k = (i >> 7) & 255;
        int n = i & 127;
        const float* Win = type ? Wi : Wu;
        float s = 0.f;
        #pragma unroll 8
        for (int j = 0; j < 128; j++)
            s = fmaf(Win[(size_t)k * 128 + j], W1[(size_t)j * 128 + n], s);
        g_wt[(type ? WT_WI : WT_WU) + n * 256 + k] = __float2half_rn(s);
    } else if (blk < 320) {
        int i = (blk - 256) * 256 + tid;
        int k = i >> 7, n = i & 127;
        g_wt[WT_W2 + n * 128 + k] = __float2half_rn(W2[(size_t)k * 128 + n]);
    } else if (blk < 352) {
        int w = (blk - 320) * 8 + (tid >> 5);
        int lane = tid & 31;
        int type = w >> 7, n = w & 127;
        const float* b = type ? bi : bu;
        float s = 0.f;
        #pragma unroll
        for (int q = 0; q < 4; q++) {
            int j = lane + q * 32;
            s = fmaf(b[j], W1[(size_t)j * 128 + n], s);
        }
        #pragma unroll
        for (int off = 16; off > 0; off >>= 1)
            s += __shfl_down_sync(0xffffffff, s, off);
        if (lane == 0) g_bfold[type][n] = s;
    } else {
        int i = (blk - 352) * 256 + tid;
        if (i < NNODE) g_deg[i] = 0;
    }
}

// ------------------------- CSR build ------------------------------------------
__global__ void build_deg(const int* __restrict__ eui, const int* __restrict__ eiu) {
    int i = blockIdx.x * blockDim.x + threadIdx.x;
    if (i < E_HALF) {
        atomicAdd(&g_deg[eui[E_HALF + i] + N_USER], 1);
    } else if (i < E_TOT) {
        atomicAdd(&g_deg[eiu[E_HALF + (i - E_HALF)]], 1);
    }
}

__global__ void scan1() {
    __shared__ int sm[1024];
    int tx = threadIdx.x;
    int i = blockIdx.x * 1024 + tx;
    int v = (i < NNODE) ? g_deg[i] : 0;
    sm[tx] = v;
    __syncthreads();
    #pragma unroll
    for (int off = 1; off < 1024; off <<= 1) {
        int t = (tx >= off) ? sm[tx - off] : 0;
        __syncthreads();
        sm[tx] += t;
        __syncthreads();
    }
    if (i < NNODE) g_rowptr[i] = sm[tx] - v;
    if (tx == 1023) g_bsums[blockIdx.x] = sm[1023];
}

__global__ void scan2k() {
    __shared__ int sm[256];
    int tx = threadIdx.x;
    int v = (tx < 196) ? g_bsums[tx] : 0;
    sm[tx] = v;
    __syncthreads();
    #pragma unroll
    for (int off = 1; off < 256; off <<= 1) {
        int t = (tx >= off) ? sm[tx - off] : 0;
        __syncthreads();
        sm[tx] += t;
        __syncthreads();
    }
    if (tx < 196) g_bsums[tx] = sm[tx] - v;
}

__global__ void scan3() {
    int tx = threadIdx.x;
    int i = blockIdx.x * 1024 + tx;
    if (i < NNODE) {
        int v = g_rowptr[i] + g_bsums[blockIdx.x];
        g_rowptr[i] = v;
        g_cursor[i] = v;
        g_dinv[i] = rsqrtf((float)(g_deg[i] + 1));
    }
    if (i == 0) g_rowptr[NNODE] = E_TOT;
}

__global__ void fill_csr(const int* __restrict__ eui, const int* __restrict__ eiu) {
    int i = blockIdx.x * blockDim.x + threadIdx.x;
    int s, d;
    if (i < E_HALF) {
        s = eui[i];
        d = eui[E_HALF + i] + N_USER;
    } else if (i < E_TOT) {
        int j = i - E_HALF;
        s = eiu[j] + N_USER;
        d = eiu[E_HALF + j];
    } else return;
    int pos = atomicAdd(&g_cursor[d], 1);
    g_col[pos] = s;
}

// ------------------------- gather helper (one warp, one node) -----------------
__device__ __forceinline__ float4 gather_node(const __half* __restrict__ hw,
                                              int node, int lane) {
    float dv = g_dinv[node];
    float ws = dv * dv;
    const __half2* self = (const __half2*)(hw + (size_t)node * HID) + lane * 2;
    float2 s0 = __half22float2(self[0]);
    float2 s1 = __half22float2(self[1]);
    float4 acc = make_float4(s0.x * ws, s0.y * ws, s1.x * ws, s1.y * ws);
    float4 acc2 = make_float4(0.f, 0.f, 0.f, 0.f);

    int e = g_rowptr[node];
    const int end = g_rowptr[node + 1];
    for (; e + 3 < end; e += 4) {
        int c0 = g_col[e], c1 = g_col[e + 1], c2 = g_col[e + 2], c3 = g_col[e + 3];
        float w0 = g_dinv[c0] * dv;
        float w1 = g_dinv[c1] * dv;
        float w2 = g_dinv[c2] * dv;
        float w3 = g_dinv[c3] * dv;
        const __half2* u0 = (const __half2*)(hw + (size_t)c0 * HID) + lane * 2;
        const __half2* u1 = (const __half2*)(hw + (size_t)c1 * HID) + lane * 2;
        const __half2* u2 = (const __half2*)(hw + (size_t)c2 * HID) + lane * 2;
        const __half2* u3 = (const __half2*)(hw + (size_t)c3 * HID) + lane * 2;
        __half2 r0a = u0[0], r0b = u0[1];
        __half2 r1a = u1[0], r1b = u1[1];
        __half2 r2a = u2[0], r2b = u2[1];
        __half2 r3a = u3[0], r3b = u3[1];
        float2 a0 = __half22float2(r0a), a1 = __half22float2(r0b);
        float2 b0 = __half22float2(r1a), b1 = __half22float2(r1b);
        float2 d0 = __half22float2(r2a), d1 = __half22float2(r2b);
        float2 f0 = __half22float2(r3a), f1 = __half22float2(r3b);
        acc.x  = fmaf(w0, a0.x, acc.x);  acc.y  = fmaf(w0, a0.y, acc.y);
        acc.z  = fmaf(w0, a1.x, acc.z);  acc.w  = fmaf(w0, a1.y, acc.w);
        acc2.x = fmaf(w1, b0.x, acc2.x); acc2.y = fmaf(w1, b0.y, acc2.y);
        acc2.z = fmaf(w1, b1.x, acc2.z); acc2.w = fmaf(w1, b1.y, acc2.w);
        acc.x  = fmaf(w2, d0.x, acc.x);  acc.y  = fmaf(w2, d0.y, acc.y);
        acc.z  = fmaf(w2, d1.x, acc.z);  acc.w  = fmaf(w2, d1.y, acc.w);
        acc2.x = fmaf(w3, f0.x, acc2.x); acc2.y = fmaf(w3, f0.y, acc2.y);
        acc2.z = fmaf(w3, f1.x, acc2.z); acc2.w = fmaf(w3, f1.y, acc2.w);
    }
    for (; e < end; e++) {
        int c0 = g_col[e];
        float w0 = g_dinv[c0] * dv;
        const __half2* u0 = (const __half2*)(hw + (size_t)c0 * HID) + lane * 2;
        float2 a0 = __half22float2(u0[0]), a1 = __half22float2(u0[1]);
        acc.x = fmaf(w0, a0.x, acc.x); acc.y = fmaf(w0, a0.y, acc.y);
        acc.z = fmaf(w0, a1.x, acc.z); acc.w = fmaf(w0, a1.y, acc.w);
    }
    acc.x += acc2.x; acc.y += acc2.y; acc.z += acc2.z; acc.w += acc2.w;
    return acc;
}

// ------------------------- proj GEMM (R12/R14 config, fp32 A path) ------------
__global__ __launch_bounds__(256, 2) void gemm_proj(
    const float* __restrict__ A0, const float* __restrict__ A1,
    const __half* __restrict__ W0, const __half* __restrict__ W1p,
    const float* __restrict__ bias, __half* __restrict__ C, int M, int nbh)
{
    constexpr int K = 256;
    constexpr int N32 = K / 32;

    extern __shared__ char smem[];
    char* sW = smem;
    char* sA = smem + WBYTES;

    const int tid = threadIdx.x, lane = tid & 31, wid = tid >> 5;
    const int m0 = (wid >> 2) * 64, n0 = (wid & 3) * 32;

    const int bx = blockIdx.x;
    const int item = bx >= nbh ? 1 : 0;
    const float* __restrict__ A = item ? A1 : A0;
    const __half* __restrict__ Wt = item ? W1p : W0;
    const int block_row = (item ? bx - nbh : bx) * 128;
    __half* __restrict__ Cc = C + (item ? (size_t)N_USER * HID : 0);
    const float* bs = bias + item * HID;

    const uint32_t sW_u = smem_u32(sW);
    const uint32_t sA_u = smem_u32(sA);

    auto stage_w = [&](int kh) {
        const uint32_t* wp = (const uint32_t*)Wt;
        #pragma unroll 4
        for (int i = tid; i < 128 * 64; i += 256) {
            int n = i >> 6, kp = i & 63;
            *(uint32_t*)(sW + n * WSTRIDE + kp * 4) = wp[n * (K / 2) + kh * 64 + kp];
        }
    };

    float acc[4][4][4];
    #pragma unroll
    for (int a = 0; a < 4; a++)
        #pragma unroll
        for (int b = 0; b < 4; b++)
            #pragma unroll
            for (int c = 0; c < 4; c++) acc[a][b][c] = 0.f;

    const uint32_t aoff = (uint32_t)((lane & 15) * ASTRIDE + ((lane & 16) ? 16 : 0));
    const uint32_t woff = (uint32_t)((((lane & 16) ? 8 : 0) + (lane & 7)) * WSTRIDE +
                                     ((lane & 8) ? 16 : 0));

    float4 vf[4];

    auto load_tile = [&](int ck) {
        #pragma unroll
        for (int q = 0; q < 4; q++) {
            int j = tid + 256 * q;
            int r = j >> 3, p = j & 7;
            int gr = block_row + r;
            if (gr > M - 1) gr = M - 1;
            vf[q] = *(const float4*)(A + (size_t)gr * K + ck * 32 + p * 4);
        }
    };
    auto store_tile = [&](int db) {
        char* buf = sA + db * ABYTES;
        #pragma unroll
        for (int q = 0; q < 4; q++) {
            int j = tid + 256 * q;
            int r = j >> 3, p = j & 7;
            uint2 o;
            o.x = h2_as_u32(__floats2half2_rn(vf[q].x, vf[q].y));
            o.y = h2_as_u32(__floats2half2_rn(vf[q].z, vf[q].w));
            *(uint2*)(buf + r * ASTRIDE + p * 8) = o;
        }
    };

    stage_w(0);
    load_tile(0);
    store_tile(0);
    __syncthreads();

    for (int i = 0; i < N32; i++) {
        if (i + 1 < N32) load_tile(i + 1);

        const uint32_t abase = sA_u + (i & 1) * ABYTES;

        #pragma unroll
        for (int c2 = 0; c2 < 2; c2++) {
            const int kk = (i * 2 + c2) & 7;
            const uint32_t wk = (uint32_t)(n0 * WSTRIDE + kk * 32) + woff;

            uint32_t wh[4][2], af[4][4];
            #pragma unroll
            for (int nt2 = 0; nt2 < 2; nt2++) {
                uint32_t q0, q1, q2, q3;
                ldsm_x4(q0, q1, q2, q3, sW_u + wk + nt2 * 16 * WSTRIDE);
                wh[nt2 * 2 + 0][0] = q0; wh[nt2 * 2 + 0][1] = q1;
                wh[nt2 * 2 + 1][0] = q2; wh[nt2 * 2 + 1][1] = q3;
            }
            #pragma unroll
            for (int mt = 0; mt < 4; mt++)
                ldsm_x4(af[mt][0], af[mt][1], af[mt][2], af[mt][3],
                        abase + (uint32_t)((m0 + mt * 16) * ASTRIDE) + aoff + c2 * 32);

            #pragma unroll
            for (int mt = 0; mt < 4; mt++)
                #pragma unroll
                for (int nt = 0; nt < 4; nt++)
                    mma16816(acc[mt][nt], af[mt], wh[nt]);
        }

        if (i + 1 < N32) store_tile((i + 1) & 1);
        __syncthreads();

        if (i == N32 / 2 - 1) {
            stage_w(1);
            __syncthreads();
        }
    }

    #pragma unroll
    for (int nt = 0; nt < 4; nt++) {
        int col = n0 + nt * 8 + 2 * (lane & 3);
        float b0 = bs[col], b1 = bs[col + 1];
        #pragma unroll
        for (int mt = 0; mt < 4; mt++) {
            int row = block_row + m0 + mt * 16 + (lane >> 2);
            if (row < M)
                *(__half2*)(Cc + (size_t)row * 128 + col) =
                    __floats2half2_rn(acc[mt][nt][0] + b0, acc[mt][nt][1] + b1);
            if (row + 8 < M)
                *(__half2*)(Cc + (size_t)(row + 8) * 128 + col) =
                    __floats2half2_rn(acc[mt][nt][2] + b0, acc[mt][nt][3] + b1);
        }
    }
}

// ------------------------- fused aggregate(relu,b1) + GEMM2 -------------------
// Phase 1: each warp gathers 16 nodes -> relu(agg+b1) -> fp16 into smem A tiles.
// Phase 2: K=128 GEMM from resident smem A against W2. Output -> Cout (g_h16).
__global__ __launch_bounds__(256, 2) void agg_gemm(
    const __half* __restrict__ hw, const __half* __restrict__ Wt,
    const float* __restrict__ b1, __half* __restrict__ Cout)
{
    extern __shared__ char smem[];
    char* sW = smem;
    char* sA = smem + WBYTES;              // 4 chunk buffers, full K=128 resident

    const int tid = threadIdx.x, lane = tid & 31, wid = tid >> 5;
    const int m0 = (wid >> 2) * 64, n0 = (wid & 3) * 32;
    const int block_row = blockIdx.x * 128;

    const uint32_t sW_u = smem_u32(sW);
    const uint32_t sA_u = smem_u32(sA);

    // stage W2
    {
        const uint32_t* wp = (const uint32_t*)Wt;
        #pragma unroll 4
        for (int i = tid; i < 128 * 64; i += 256) {
            int n = i >> 6, kp = i & 63;
            *(uint32_t*)(sW + n * WSTRIDE + kp * 4) = wp[n * 64 + kp];
        }
    }

    // phase 1: aggregate 16 nodes per warp into smem A chunks
    {
        float4 bv = ((const float4*)b1)[lane];
        const uint32_t dst_base = sA_u + (uint32_t)(lane >> 3) * ABYTES +
                                  (uint32_t)(((lane * 4) & 31) * 2);
        for (int t = 0; t < 16; t++) {
            int r = wid * 16 + t;
            int node = block_row + r;
            float4 acc;
            if (node < NNODE) {
                acc = gather_node(hw, node, lane);
                acc.x = fmaxf(acc.x + bv.x, 0.f);
                acc.y = fmaxf(acc.y + bv.y, 0.f);
                acc.z = fmaxf(acc.z + bv.z, 0.f);
                acc.w = fmaxf(acc.w + bv.w, 0.f);
            } else {
                acc = make_float4(0.f, 0.f, 0.f, 0.f);
            }
            uint32_t o0 = h2_as_u32(__floats2half2_rn(acc.x, acc.y));
            uint32_t o1 = h2_as_u32(__floats2half2_rn(acc.z, acc.w));
            asm volatile("st.shared.v2.u32 [%0], {%1, %2};"
                         :: "r"(dst_base + (uint32_t)r * ASTRIDE), "r"(o0), "r"(o1)
                         : "memory");
        }
    }
    __syncthreads();

    // phase 2: GEMM from resident A
    float acc[4][4][4];
    #pragma unroll
    for (int a = 0; a < 4; a++)
        #pragma unroll
        for (int b = 0; b < 4; b++)
            #pragma unroll
            for (int c = 0; c < 4; c++) acc[a][b][c] = 0.f;

    const uint32_t aoff = (uint32_t)((lane & 15) * ASTRIDE + ((lane & 16) ? 16 : 0));
    const uint32_t woff = (uint32_t)((((lane & 16) ? 8 : 0) + (lane & 7)) * WSTRIDE +
                                     ((lane & 8) ? 16 : 0));

    for (int i = 0; i < 4; i++) {
        const uint32_t abase = sA_u + i * ABYTES;
        #pragma unroll
        for (int c2 = 0; c2 < 2; c2++) {
            const int kk = i * 2 + c2;
            const uint32_t wk = (uint32_t)(n0 * WSTRIDE + kk * 32) + woff;

            uint32_t wh[4][2], af[4][4];
            #pragma unroll
            for (int nt2 = 0; nt2 < 2; nt2++) {
                uint32_t q0, q1, q2, q3;
                ldsm_x4(q0, q1, q2, q3, sW_u + wk + nt2 * 16 * WSTRIDE);
                wh[nt2 * 2 + 0][0] = q0; wh[nt2 * 2 + 0][1] = q1;
                wh[nt2 * 2 + 1][0] = q2; wh[nt2 * 2 + 1][1] = q3;
            }
            #pragma unroll
            for (int mt = 0; mt < 4; mt++)
                ldsm_x4(af[mt][0], af[mt][1], af[mt][2], af[mt][3],
                        abase + (uint32_t)((m0 + mt * 16) * ASTRIDE) + aoff + c2 * 32);

            #pragma unroll
            for (int mt = 0; mt < 4; mt++)
                #pragma unroll
                for (int nt = 0; nt < 4; nt++)
                    mma16816(acc[mt][nt], af[mt], wh[nt]);
        }
    }

    // epilogue -> Cout (no bias; b2 added in final aggregate)
    #pragma unroll
    for (int nt = 0; nt < 4; nt++) {
        int col = n0 + nt * 8 + 2 * (lane & 3);
        #pragma unroll
        for (int mt = 0; mt < 4; mt++) {
            int row = block_row + m0 + mt * 16 + (lane >> 2);
            if (row < NNODE)
                *(__half2*)(Cout + (size_t)row * 128 + col) =
                    __floats2half2_rn(acc[mt][nt][0], acc[mt][nt][1]);
            if (row + 8 < NNODE)
                *(__half2*)(Cout + (size_t)(row + 8) * 128 + col) =
                    __floats2half2_rn(acc[mt][nt][2], acc[mt][nt][3]);
        }
    }
}

// ------------------------- final aggregation ----------------------------------
__global__ __launch_bounds__(256)
void aggregate_out(const __half* __restrict__ hw, float* __restrict__ out,
                   const float* __restrict__ bias) {
    int node = (blockIdx.x * blockDim.x + threadIdx.x) >> 5;
    int lane = threadIdx.x & 31;
    if (node >= NNODE) return;

    float4 acc = gather_node(hw, node, lane);
    float4 b = ((const float4*)bias)[lane];
    acc.x += b.x; acc.y += b.y; acc.z += b.z; acc.w += b.w;
    ((float4*)(out + (size_t)node * HID))[lane] = acc;
}

// ------------------------- driver --------------------------------------------
extern "C" void kernel_launch(void* const* d_in, const int* in_sizes, int n_in,
                              void* d_out, int out_size) {
    const float* x_user    = (const float*)d_in[0];
    const float* x_item    = (const float*)d_in[1];
    const int*   edge_ui   = (const int*)d_in[2];
    const int*   edge_iu   = (const int*)d_in[3];
    const float* W_in_user = (const float*)d_in[4];
    const float* b_in_user = (const float*)d_in[5];
    const float* W_in_item = (const float*)d_in[6];
    const float* b_in_item = (const float*)d_in[7];
    const float* W1        = (const float*)d_in[8];
    const float* b1        = (const float*)d_in[9];
    const float* W2        = (const float*)d_in[10];
    const float* b2        = (const float*)d_in[11];
    float* out = (float*)d_out;

    __half* hw16; __half* h16;
    __half* wt;
    float* bfold;
    cudaGetSymbolAddress((void**)&hw16,  g_hw16);
    cudaGetSymbolAddress((void**)&h16,   g_h16);
    cudaGetSymbolAddress((void**)&wt,    g_wt);
    cudaGetSymbolAddress((void**)&bfold, g_bfold);

    const int SMEM_PROJ = WBYTES + 2 * ABYTES;   // 55296
    const int SMEM_AG   = WBYTES + 4 * ABYTES;   // 75776
    cudaFuncSetAttribute((const void*)gemm_proj,
                         cudaFuncAttributeMaxDynamicSharedMemorySize, SMEM_PROJ);
    cudaFuncSetAttribute((const void*)agg_gemm,
                         cudaFuncAttributeMaxDynamicSharedMemorySize, SMEM_AG);

    const int NB_SCAN = (NNODE + 1023) / 1024;  // 196
    const int NB_ZERO = (NNODE + 255) / 256;    // 782
    const int NBU = (N_USER + 127) / 128;       // 782
    const int NB2 = (NNODE + 127) / 128;        // 1563

    // (1) fused prep
    prep_all<<<352 + NB_ZERO, 256>>>(W_in_user, W_in_item, W1, W2, b_in_user, b_in_item);
    // (2) degree histogram
    build_deg<<<(E_TOT + 255) / 256, 256>>>(edge_ui, edge_iu);
    // (3) scan stage 1
    scan1<<<NB_SCAN, 1024>>>();
    // (4) merged proj GEMM (user + item) -> hw16
    gemm_proj<<<2 * NBU, 256, SMEM_PROJ>>>(
        x_user, x_item, wt + WT_WU, wt + WT_WI, bfold, hw16, N_USER, NBU);
    // (5) scan stage 2
    scan2k<<<1, 256>>>();
    // (6) scan stage 3 + dinv
    scan3<<<NB_SCAN, 1024>>>();
    // (7) fill CSR
    fill_csr<<<(E_TOT + 255) / 256, 256>>>(edge_ui, edge_iu);
    // (8) fused aggregate(b1,relu) + GEMM2 -> h16
    agg_gemm<<<NB2, 256, SMEM_AG>>>(hw16, wt + WT_W2, b1, h16);
    // (9) final aggregate + b2 -> out (fp32)
    aggregate_out<<<(NNODE * 32 + 255) / 256, 256>>>(h16, out, b2);
}

// round 16
// speedup vs baseline: 1.1694x; 1.1694x over previous
#include <cuda_runtime.h>
#include <cuda_fp16.h>
#include <math.h>
#include <stdint.h>
#include <string.h>

#define N_USER 100000
#define N_ITEM 100000
#define NNODE  200000
#define E_HALF 600000
#define E_TOT  1200000
#define HID 128

// ------------------------- scratch (device globals, no alloc) ----------------
__device__ __half g_hw16[(size_t)NNODE * HID];   // pre-aggregation features
__device__ __half g_h16[(size_t)NNODE * HID];    // layer-1 activations (fp16)
__device__ float  g_dinv[NNODE];
__device__ int    g_deg[NNODE];
__device__ int    g_rowptr[NNODE + 1];
__device__ int    g_cursor[NNODE];
__device__ int    g_col[E_TOT];
__device__ int    g_bsums[256];
__device__ float  g_bfold[2][HID];               // b_in @ W1 per node type

// fp16 weights, transposed Wt[n][k]
#define WT_WU 0
#define WT_WI 32768
#define WT_W2 65536
__device__ __half g_wt[81920];

// ------------------------- helpers -------------------------------------------
__device__ __forceinline__ uint32_t smem_u32(const void* p) {
    uint32_t a;
    asm("{ .reg .u64 t; cvta.to.shared.u64 t, %1; cvt.u32.u64 %0, t; }" : "=r"(a) : "l"(p));
    return a;
}

__device__ __forceinline__ uint32_t h2_as_u32(__half2 h) {
    uint32_t u;
    memcpy(&u, &h, 4);
    return u;
}

__device__ __forceinline__ void ldsm_x4(uint32_t& r0, uint32_t& r1,
                                        uint32_t& r2, uint32_t& r3, uint32_t addr) {
    asm volatile("ldmatrix.sync.aligned.m8n8.x4.shared.b16 {%0,%1,%2,%3}, [%4];"
                 : "=r"(r0), "=r"(r1), "=r"(r2), "=r"(r3) : "r"(addr));
}

__device__ __forceinline__ void mma16816(float* c, const uint32_t* a, const uint32_t* b) {
    asm volatile("mma.sync.aligned.m16n8k16.row.col.f32.f16.f16.f32 "
                 "{%0,%1,%2,%3}, {%4,%5,%6,%7}, {%8,%9}, {%0,%1,%2,%3};"
                 : "+f"(c[0]), "+f"(c[1]), "+f"(c[2]), "+f"(c[3])
                 : "r"(a[0]), "r"(a[1]), "r"(a[2]), "r"(a[3]), "r"(b[0]), "r"(b[1]));
}

__device__ __forceinline__ void cp_async16(uint32_t saddr, const void* g) {
    asm volatile("cp.async.cg.shared.global [%0], [%1], 16;" :: "r"(saddr), "l"(g));
}
__device__ __forceinline__ void cp_commit() {
    asm volatile("cp.async.commit_group;" ::: "memory");
}
__device__ __forceinline__ void cp_wait0() {
    asm volatile("cp.async.wait_group 0;" ::: "memory");
}

// ------------------------- fused prep -----------------------------------------
__global__ void prep_all(const float* __restrict__ Wu, const float* __restrict__ Wi,
                         const float* __restrict__ W1, const float* __restrict__ W2,
                         const float* __restrict__ bu, const float* __restrict__ bi) {
    int blk = blockIdx.x, tid = threadIdx.x;
    if (blk < 256) {
        int i = blk * 256 + tid;
        int type = i >> 15;
        int k = (i >> 7) & 255;
        int n = i & 127;
        const float* Win = type ? Wi : Wu;
        float s = 0.f;
        #pragma unroll 8
        for (int j = 0; j < 128; j++)
            s = fmaf(Win[(size_t)k * 128 + j], W1[(size_t)j * 128 + n], s);
        g_wt[(type ? WT_WI : WT_WU) + n * 256 + k] = __float2half_rn(s);
    } else if (blk < 320) {
        int i = (blk - 256) * 256 + tid;
        int k = i >> 7, n = i & 127;
        g_wt[WT_W2 + n * 128 + k] = __float2half_rn(W2[(size_t)k * 128 + n]);
    } else if (blk < 352) {
        int w = (blk - 320) * 8 + (tid >> 5);
        int lane = tid & 31;
        int type = w >> 7, n = w & 127;
        const float* b = type ? bi : bu;
        float s = 0.f;
        #pragma unroll
        for (int q = 0; q < 4; q++) {
            int j = lane + q * 32;
            s = fmaf(b[j], W1[(size_t)j * 128 + n], s);
        }
        #pragma unroll
        for (int off = 16; off > 0; off >>= 1)
            s += __shfl_down_sync(0xffffffff, s, off);
        if (lane == 0) g_bfold[type][n] = s;
    } else {
        int i = (blk - 352) * 256 + tid;
        if (i < NNODE) g_deg[i] = 0;
    }
}

// ------------------------- CSR build ------------------------------------------
__global__ void build_deg(const int* __restrict__ eui, const int* __restrict__ eiu) {
    int i = blockIdx.x * blockDim.x + threadIdx.x;
    if (i < E_HALF) {
        atomicAdd(&g_deg[eui[E_HALF + i] + N_USER], 1);
    } else if (i < E_TOT) {
        atomicAdd(&g_deg[eiu[E_HALF + (i - E_HALF)]], 1);
    }
}

__global__ void scan1() {
    __shared__ int sm[1024];
    int tx = threadIdx.x;
    int i = blockIdx.x * 1024 + tx;
    int v = (i < NNODE) ? g_deg[i] : 0;
    sm[tx] = v;
    __syncthreads();
    #pragma unroll
    for (int off = 1; off < 1024; off <<= 1) {
        int t = (tx >= off) ? sm[tx - off] : 0;
        __syncthreads();
        sm[tx] += t;
        __syncthreads();
    }
    if (i < NNODE) g_rowptr[i] = sm[tx] - v;
    if (tx == 1023) g_bsums[blockIdx.x] = sm[1023];
}

__global__ void scan2k() {
    __shared__ int sm[256];
    int tx = threadIdx.x;
    int v = (tx < 196) ? g_bsums[tx] : 0;
    sm[tx] = v;
    __syncthreads();
    #pragma unroll
    for (int off = 1; off < 256; off <<= 1) {
        int t = (tx >= off) ? sm[tx - off] : 0;
        __syncthreads();
        sm[tx] += t;
        __syncthreads();
    }
    if (tx < 196) g_bsums[tx] = sm[tx] - v;
}

__global__ void scan3() {
    int tx = threadIdx.x;
    int i = blockIdx.x * 1024 + tx;
    if (i < NNODE) {
        int v = g_rowptr[i] + g_bsums[blockIdx.x];
        g_rowptr[i] = v;
        g_cursor[i] = v;
        g_dinv[i] = rsqrtf((float)(g_deg[i] + 1));
    }
    if (i == 0) g_rowptr[NNODE] = E_TOT;
}

__global__ void fill_csr(const int* __restrict__ eui, const int* __restrict__ eiu) {
    int i = blockIdx.x * blockDim.x + threadIdx.x;
    int s, d;
    if (i < E_HALF) {
        s = eui[i];
        d = eui[E_HALF + i] + N_USER;
    } else if (i < E_TOT) {
        int j = i - E_HALF;
        s = eiu[j] + N_USER;
        d = eiu[E_HALF + j];
    } else return;
    int pos = atomicAdd(&g_cursor[d], 1);
    g_col[pos] = s;
}

// ------------------------- HMMA GEMM (R12/R14 config) -------------------------
// C[M,128] = A[M,K] @ W[K,128]; A fp16 exact, W plain fp16 (single product).
// M-tile 128 (2 CTAs/SM), warp tile 64x32; K-step 32; cp.async for fp16 A;
// DUAL merges user+item proj.
template <int K, bool BIAS, typename AT, bool DUAL>
__global__ __launch_bounds__(256, 2) void gemm_mma(
    const AT* __restrict__ A0, const AT* __restrict__ A1,
    const __half* __restrict__ W0, const __half* __restrict__ W1p,
    const float* __restrict__ bias, __half* __restrict__ C, int M, int nbh)
{
    constexpr int WSTRIDE = 272;           // 128 halves + 8 pad
    constexpr int WBYTES  = 128 * WSTRIDE; // 34816
    constexpr int ASTRIDE = 80;            // 32 halves + 8 pad
    constexpr int ABYTES  = 128 * ASTRIDE; // 10240
    constexpr int N32     = K / 32;

    extern __shared__ char smem[];
    char* sW = smem;
    char* sA = smem + WBYTES;              // 2 double-buffered 32-K A tiles

    const int tid = threadIdx.x, lane = tid & 31, wid = tid >> 5;
    const int m0 = (wid >> 2) * 64, n0 = (wid & 3) * 32;

    const int bx = blockIdx.x;
    const int item = DUAL ? (bx >= nbh ? 1 : 0) : 0;
    const AT* __restrict__ A = item ? A1 : A0;
    const __half* __restrict__ Wt = item ? W1p : W0;
    const int block_row = ((DUAL && item) ? bx - nbh : bx) * 128;
    __half* __restrict__ Cc = C + (item ? (size_t)N_USER * HID : 0);
    const float* bs = bias + (DUAL ? item * HID : 0);

    const uint32_t sW_u = smem_u32(sW);
    const uint32_t sA_u = smem_u32(sA);

    auto stage_w = [&](int kh) {
        const uint32_t* wp = (const uint32_t*)Wt;
        #pragma unroll 4
        for (int i = tid; i < 128 * 64; i += 256) {
            int n = i >> 6, kp = i & 63;
            *(uint32_t*)(sW + n * WSTRIDE + kp * 4) = wp[n * (K / 2) + kh * 64 + kp];
        }
    };

    float acc[4][4][4];
    #pragma unroll
    for (int a = 0; a < 4; a++)
        #pragma unroll
        for (int b = 0; b < 4; b++)
            #pragma unroll
            for (int c = 0; c < 4; c++) acc[a][b][c] = 0.f;

    const uint32_t aoff = (uint32_t)((lane & 15) * ASTRIDE + ((lane & 16) ? 16 : 0));
    const uint32_t woff = (uint32_t)((((lane & 16) ? 8 : 0) + (lane & 7)) * WSTRIDE +
                                     ((lane & 8) ? 16 : 0));

    float4 vf[4];   // fp32 staging registers (proj path)

    auto load_tile = [&](int ck) {       // fp32 path: LDG into regs
        #pragma unroll
        for (int q = 0; q < 4; q++) {
            int j = tid + 256 * q;
            int r = j >> 3, p = j & 7;
            int gr = block_row + r;
            if (gr > M - 1) gr = M - 1;
            vf[q] = *(const float4*)((const float*)A + (size_t)gr * K + ck * 32 + p * 4);
        }
    };
    auto store_tile = [&](int db) {      // fp32 path: convert + STS
        char* buf = sA + db * ABYTES;
        #pragma unroll
        for (int q = 0; q < 4; q++) {
            int j = tid + 256 * q;
            int r = j >> 3, p = j & 7;
            uint2 o;
            o.x = h2_as_u32(__floats2half2_rn(vf[q].x, vf[q].y));
            o.y = h2_as_u32(__floats2half2_rn(vf[q].z, vf[q].w));
            *(uint2*)(buf + r * ASTRIDE + p * 8) = o;
        }
    };
    auto cp_tile = [&](int ck, int db) { // fp16 path: cp.async direct
        uint32_t base = sA_u + db * ABYTES;
        #pragma unroll
        for (int q = 0; q < 2; q++) {
            int j = tid + 256 * q;
            int r = j >> 2, p = j & 3;
            int gr = block_row + r;
            if (gr > M - 1) gr = M - 1;
            cp_async16(base + r * ASTRIDE + p * 16,
                       (const __half*)A + (size_t)gr * K + ck * 32 + p * 8);
        }
        cp_commit();
    };

    // prologue
    stage_w(0);
    if constexpr (sizeof(AT) == 2) {
        cp_tile(0, 0);
        cp_wait0();
    } else {
        load_tile(0);
        store_tile(0);
    }
    __syncthreads();

    for (int i = 0; i < N32; i++) {
        if (i + 1 < N32) {
            if constexpr (sizeof(AT) == 2) cp_tile(i + 1, (i + 1) & 1);
            else load_tile(i + 1);
        }

        const uint32_t abase = sA_u + (i & 1) * ABYTES;

        #pragma unroll
        for (int c2 = 0; c2 < 2; c2++) {
            const int kk = (i * 2 + c2) & 7;
            const uint32_t wk = (uint32_t)(n0 * WSTRIDE + kk * 32) + woff;

            uint32_t wh[4][2], af[4][4];
            #pragma unroll
            for (int nt2 = 0; nt2 < 2; nt2++) {
                uint32_t q0, q1, q2, q3;
                ldsm_x4(q0, q1, q2, q3, sW_u + wk + nt2 * 16 * WSTRIDE);
                wh[nt2 * 2 + 0][0] = q0; wh[nt2 * 2 + 0][1] = q1;
                wh[nt2 * 2 + 1][0] = q2; wh[nt2 * 2 + 1][1] = q3;
            }
            #pragma unroll
            for (int mt = 0; mt < 4; mt++)
                ldsm_x4(af[mt][0], af[mt][1], af[mt][2], af[mt][3],
                        abase + (uint32_t)((m0 + mt * 16) * ASTRIDE) + aoff + c2 * 32);

            #pragma unroll
            for (int mt = 0; mt < 4; mt++)
                #pragma unroll
                for (int nt = 0; nt < 4; nt++)
                    mma16816(acc[mt][nt], af[mt], wh[nt]);
        }

        if (i + 1 < N32) {
            if constexpr (sizeof(AT) == 2) cp_wait0();
            else store_tile((i + 1) & 1);
        }
        __syncthreads();

        if constexpr (K > 128) {
            if (i == N32 / 2 - 1) {
                stage_w(1);
                __syncthreads();
            }
        }
    }

    // epilogue: fp16 out
    #pragma unroll
    for (int nt = 0; nt < 4; nt++) {
        int col = n0 + nt * 8 + 2 * (lane & 3);
        float b0 = 0.f, b1 = 0.f;
        if (BIAS) { b0 = bs[col]; b1 = bs[col + 1]; }
        #pragma unroll
        for (int mt = 0; mt < 4; mt++) {
            int row = block_row + m0 + mt * 16 + (lane >> 2);
            if (row < M)
                *(__half2*)(Cc + (size_t)row * 128 + col) =
                    __floats2half2_rn(acc[mt][nt][0] + b0, acc[mt][nt][1] + b1);
            if (row + 8 < M)
                *(__half2*)(Cc + (size_t)(row + 8) * 128 + col) =
                    __floats2half2_rn(acc[mt][nt][2] + b0, acc[mt][nt][3] + b1);
        }
    }
}

// ------------------------- aggregation: one warp per dst node ----------------
// Fully predicated 4-batch gather: all 8 row loads of every batch issue
// concurrently; tail lanes get zero weight and a safe (clamped) index.
template <typename OUTT>
__global__ __launch_bounds__(256)
void aggregate(const __half* __restrict__ hw, OUTT* __restrict__ out,
               const float* __restrict__ bias, int relu) {
    int node = (blockIdx.x * blockDim.x + threadIdx.x) >> 5;
    int lane = threadIdx.x & 31;
    if (node >= NNODE) return;

    float dv = g_dinv[node];
    float ws = dv * dv;

    const __half2* self = (const __half2*)(hw + (size_t)node * HID) + lane * 2;
    float2 s0 = __half22float2(self[0]);
    float2 s1 = __half22float2(self[1]);
    float4 acc = make_float4(s0.x * ws, s0.y * ws, s1.x * ws, s1.y * ws);
    float4 acc2 = make_float4(0.f, 0.f, 0.f, 0.f);

    int e = g_rowptr[node];
    const int end = g_rowptr[node + 1];

    for (; e < end; e += 4) {
        int e1i = e + 1, e2i = e + 2, e3i = e + 3;
        bool v1 = e1i < end, v2 = e2i < end, v3 = e3i < end;
        int c0 = g_col[e];
        int c1 = v1 ? g_col[e1i] : c0;
        int c2 = v2 ? g_col[e2i] : c0;
        int c3 = v3 ? g_col[e3i] : c0;
        float w0 = g_dinv[c0] * dv;
        float w1 = v1 ? g_dinv[c1] * dv : 0.f;
        float w2 = v2 ? g_dinv[c2] * dv : 0.f;
        float w3 = v3 ? g_dinv[c3] * dv : 0.f;
        const __half2* u0 = (const __half2*)(hw + (size_t)c0 * HID) + lane * 2;
        const __half2* u1 = (const __half2*)(hw + (size_t)c1 * HID) + lane * 2;
        const __half2* u2 = (const __half2*)(hw + (size_t)c2 * HID) + lane * 2;
        const __half2* u3 = (const __half2*)(hw + (size_t)c3 * HID) + lane * 2;
        __half2 r0a = u0[0], r0b = u0[1];
        __half2 r1a = u1[0], r1b = u1[1];
        __half2 r2a = u2[0], r2b = u2[1];
        __half2 r3a = u3[0], r3b = u3[1];
        float2 a0 = __half22float2(r0a), a1 = __half22float2(r0b);
        float2 b0 = __half22float2(r1a), b1 = __half22float2(r1b);
        float2 d0 = __half22float2(r2a), d1 = __half22float2(r2b);
        float2 f0 = __half22float2(r3a), f1 = __half22float2(r3b);
        acc.x  = fmaf(w0, a0.x, acc.x);  acc.y  = fmaf(w0, a0.y, acc.y);
        acc.z  = fmaf(w0, a1.x, acc.z);  acc.w  = fmaf(w0, a1.y, acc.w);
        acc2.x = fmaf(w1, b0.x, acc2.x); acc2.y = fmaf(w1, b0.y, acc2.y);
        acc2.z = fmaf(w1, b1.x, acc2.z); acc2.w = fmaf(w1, b1.y, acc2.w);
        acc.x  = fmaf(w2, d0.x, acc.x);  acc.y  = fmaf(w2, d0.y, acc.y);
        acc.z  = fmaf(w2, d1.x, acc.z);  acc.w  = fmaf(w2, d1.y, acc.w);
        acc2.x = fmaf(w3, f0.x, acc2.x); acc2.y = fmaf(w3, f0.y, acc2.y);
        acc2.z = fmaf(w3, f1.x, acc2.z); acc2.w = fmaf(w3, f1.y, acc2.w);
    }
    acc.x += acc2.x; acc.y += acc2.y; acc.z += acc2.z; acc.w += acc2.w;

    float4 b = ((const float4*)bias)[lane];
    acc.x += b.x; acc.y += b.y; acc.z += b.z; acc.w += b.w;
    if (relu) {
        acc.x = fmaxf(acc.x, 0.f); acc.y = fmaxf(acc.y, 0.f);
        acc.z = fmaxf(acc.z, 0.f); acc.w = fmaxf(acc.w, 0.f);
    }
    if constexpr (sizeof(OUTT) == 4) {
        ((float4*)((float*)out + (size_t)node * HID))[lane] = acc;
    } else {
        __half2* op = (__half2*)((__half*)out + (size_t)node * HID) + lane * 2;
        op[0] = __floats2half2_rn(acc.x, acc.y);
        op[1] = __floats2half2_rn(acc.z, acc.w);
    }
}

// ------------------------- driver --------------------------------------------
extern "C" void kernel_launch(void* const* d_in, const int* in_sizes, int n_in,
                              void* d_out, int out_size) {
    const float* x_user    = (const float*)d_in[0];
    const float* x_item    = (const float*)d_in[1];
    const int*   edge_ui   = (const int*)d_in[2];
    const int*   edge_iu   = (const int*)d_in[3];
    const float* W_in_user = (const float*)d_in[4];
    const float* b_in_user = (const float*)d_in[5];
    const float* W_in_item = (const float*)d_in[6];
    const float* b_in_item = (const float*)d_in[7];
    const float* W1        = (const float*)d_in[8];
    const float* b1        = (const float*)d_in[9];
    const float* W2        = (const float*)d_in[10];
    const float* b2        = (const float*)d_in[11];
    float* out = (float*)d_out;

    __half* hw16; __half* h16;
    __half* wt;
    float* bfold;
    cudaGetSymbolAddress((void**)&hw16,  g_hw16);
    cudaGetSymbolAddress((void**)&h16,   g_h16);
    cudaGetSymbolAddress((void**)&wt,    g_wt);
    cudaGetSymbolAddress((void**)&bfold, g_bfold);

    const int SMEM_GEMM = 34816 + 2 * 10240;   // 55296
    cudaFuncSetAttribute((const void*)gemm_mma<256, true, float, true>,
                         cudaFuncAttributeMaxDynamicSharedMemorySize, SMEM_GEMM);
    cudaFuncSetAttribute((const void*)gemm_mma<128, false, __half, false>,
                         cudaFuncAttributeMaxDynamicSharedMemorySize, SMEM_GEMM);

    const int NB_SCAN = (NNODE + 1023) / 1024;  // 196
    const int NB_ZERO = (NNODE + 255) / 256;    // 782
    const int NBU = (N_USER + 127) / 128;       // 782
    const int NB2 = (NNODE + 127) / 128;        // 1563

    // (1) fused prep
    prep_all<<<352 + NB_ZERO, 256>>>(W_in_user, W_in_item, W1, W2, b_in_user, b_in_item);
    // (2) degree histogram
    build_deg<<<(E_TOT + 255) / 256, 256>>>(edge_ui, edge_iu);
    // (3) scan stage 1
    scan1<<<NB_SCAN, 1024>>>();
    // (4) merged proj GEMM (user + item)
    gemm_mma<256, true, float, true><<<2 * NBU, 256, SMEM_GEMM>>>(
        x_user, x_item, wt + WT_WU, wt + WT_WI, bfold, hw16, N_USER, NBU);
    // (5) scan stage 2
    scan2k<<<1, 256>>>();
    // (6) scan stage 3 + dinv
    scan3<<<NB_SCAN, 1024>>>();
    // (7) fill CSR
    fill_csr<<<(E_TOT + 255) / 256, 256>>>(edge_ui, edge_iu);
    // (8) layer-1 aggregate -> h16 (fp16, relu)
    aggregate<__half><<<(NNODE * 32 + 255) / 256, 256>>>(hw16, h16, b1, 1);
    // (9) layer-2 GEMM (fp16 A via cp.async)
    gemm_mma<128, false, __half, false><<<NB2, 256, SMEM_GEMM>>>(
        h16, h16, wt + WT_W2, wt + WT_W2, b2, hw16, NNODE, NB2);
    // (10) layer-2 aggregate -> out (fp32)
    aggregate<float><<<(NNODE * 32 + 255) / 256, 256>>>(hw16, out, b2, 0);
}

// round 17
// speedup vs baseline: 1.2306x; 1.0523x over previous
#include <cuda_runtime.h>
#include <cuda_fp16.h>
#include <math.h>
#include <stdint.h>
#include <string.h>

#define N_USER 100000
#define N_ITEM 100000
#define NNODE  200000
#define E_HALF 600000
#define E_TOT  1200000
#define HID 128

// ------------------------- scratch (device globals, no alloc) ----------------
__device__ __half g_hw16[(size_t)NNODE * HID];   // pre-aggregation features
__device__ __half g_h16[(size_t)NNODE * HID];    // layer-1 activations (fp16)
__device__ float  g_dinv[NNODE];
__device__ int    g_deg[NNODE];
__device__ int    g_rowptr[NNODE + 1];
__device__ int    g_cursor[NNODE];
__device__ int    g_col[E_TOT];
__device__ int    g_bsums[256];
__device__ float  g_bfold[2][HID];               // b_in @ W1 per node type

// fp16 weights, transposed Wt[n][k]
#define WT_WU 0
#define WT_WI 32768
#define WT_W2 65536
__device__ __half g_wt[81920];

// ------------------------- helpers -------------------------------------------
__device__ __forceinline__ uint32_t smem_u32(const void* p) {
    uint32_t a;
    asm("{ .reg .u64 t; cvta.to.shared.u64 t, %1; cvt.u32.u64 %0, t; }" : "=r"(a) : "l"(p));
    return a;
}

__device__ __forceinline__ uint32_t h2_as_u32(__half2 h) {
    uint32_t u;
    memcpy(&u, &h, 4);
    return u;
}

__device__ __forceinline__ void ldsm_x4(uint32_t& r0, uint32_t& r1,
                                        uint32_t& r2, uint32_t& r3, uint32_t addr) {
    asm volatile("ldmatrix.sync.aligned.m8n8.x4.shared.b16 {%0,%1,%2,%3}, [%4];"
                 : "=r"(r0), "=r"(r1), "=r"(r2), "=r"(r3) : "r"(addr));
}

__device__ __forceinline__ void mma16816(float* c, const uint32_t* a, const uint32_t* b) {
    asm volatile("mma.sync.aligned.m16n8k16.row.col.f32.f16.f16.f32 "
                 "{%0,%1,%2,%3}, {%4,%5,%6,%7}, {%8,%9}, {%0,%1,%2,%3};"
                 : "+f"(c[0]), "+f"(c[1]), "+f"(c[2]), "+f"(c[3])
                 : "r"(a[0]), "r"(a[1]), "r"(a[2]), "r"(a[3]), "r"(b[0]), "r"(b[1]));
}

__device__ __forceinline__ void cp_async16(uint32_t saddr, const void* g) {
    asm volatile("cp.async.cg.shared.global [%0], [%1], 16;" :: "r"(saddr), "l"(g));
}
__device__ __forceinline__ void cp_commit() {
    asm volatile("cp.async.commit_group;" ::: "memory");
}
__device__ __forceinline__ void cp_wait0() {
    asm volatile("cp.async.wait_group 0;" ::: "memory");
}

// ------------------------- weight prep (stream 0) -----------------------------
__global__ void prep_weights(const float* __restrict__ Wu, const float* __restrict__ Wi,
                             const float* __restrict__ W1, const float* __restrict__ W2,
                             const float* __restrict__ bu, const float* __restrict__ bi) {
    int blk = blockIdx.x, tid = threadIdx.x;
    if (blk < 256) {
        int i = blk * 256 + tid;
        int type = i >> 15;
        int k = (i >> 7) & 255;
        int n = i & 127;
        const float* Win = type ? Wi : Wu;
        float s = 0.f;
        #pragma unroll 8
        for (int j = 0; j < 128; j++)
            s = fmaf(Win[(size_t)k * 128 + j], W1[(size_t)j * 128 + n], s);
        g_wt[(type ? WT_WI : WT_WU) + n * 256 + k] = __float2half_rn(s);
    } else if (blk < 320) {
        int i = (blk - 256) * 256 + tid;
        int k = i >> 7, n = i & 127;
        g_wt[WT_W2 + n * 128 + k] = __float2half_rn(W2[(size_t)k * 128 + n]);
    } else {
        int w = (blk - 320) * 8 + (tid >> 5);
        int lane = tid & 31;
        int type = w >> 7, n = w & 127;
        const float* b = type ? bi : bu;
        float s = 0.f;
        #pragma unroll
        for (int q = 0; q < 4; q++) {
            int j = lane + q * 32;
            s = fmaf(b[j], W1[(size_t)j * 128 + n], s);
        }
        #pragma unroll
        for (int off = 16; off > 0; off >>= 1)
            s += __shfl_down_sync(0xffffffff, s, off);
        if (lane == 0) g_bfold[type][n] = s;
    }
}

// ------------------------- CSR build (stream 2) -------------------------------
__global__ void zero_deg() {
    int i = blockIdx.x * blockDim.x + threadIdx.x;
    if (i < NNODE) g_deg[i] = 0;
}

__global__ void build_deg(const int* __restrict__ eui, const int* __restrict__ eiu) {
    int i = blockIdx.x * blockDim.x + threadIdx.x;
    if (i < E_HALF) {
        atomicAdd(&g_deg[eui[E_HALF + i] + N_USER], 1);
    } else if (i < E_TOT) {
        atomicAdd(&g_deg[eiu[E_HALF + (i - E_HALF)]], 1);
    }
}

__global__ void scan1() {
    __shared__ int sm[1024];
    int tx = threadIdx.x;
    int i = blockIdx.x * 1024 + tx;
    int v = (i < NNODE) ? g_deg[i] : 0;
    sm[tx] = v;
    __syncthreads();
    #pragma unroll
    for (int off = 1; off < 1024; off <<= 1) {
        int t = (tx >= off) ? sm[tx - off] : 0;
        __syncthreads();
        sm[tx] += t;
        __syncthreads();
    }
    if (i < NNODE) g_rowptr[i] = sm[tx] - v;
    if (tx == 1023) g_bsums[blockIdx.x] = sm[1023];
}

__global__ void scan2k() {
    __shared__ int sm[256];
    int tx = threadIdx.x;
    int v = (tx < 196) ? g_bsums[tx] : 0;
    sm[tx] = v;
    __syncthreads();
    #pragma unroll
    for (int off = 1; off < 256; off <<= 1) {
        int t = (tx >= off) ? sm[tx - off] : 0;
        __syncthreads();
        sm[tx] += t;
        __syncthreads();
    }
    if (tx < 196) g_bsums[tx] = sm[tx] - v;
}

__global__ void scan3() {
    int tx = threadIdx.x;
    int i = blockIdx.x * 1024 + tx;
    if (i < NNODE) {
        int v = g_rowptr[i] + g_bsums[blockIdx.x];
        g_rowptr[i] = v;
        g_cursor[i] = v;
        g_dinv[i] = rsqrtf((float)(g_deg[i] + 1));
    }
    if (i == 0) g_rowptr[NNODE] = E_TOT;
}

__global__ void fill_csr(const int* __restrict__ eui, const int* __restrict__ eiu) {
    int i = blockIdx.x * blockDim.x + threadIdx.x;
    int s, d;
    if (i < E_HALF) {
        s = eui[i];
        d = eui[E_HALF + i] + N_USER;
    } else if (i < E_TOT) {
        int j = i - E_HALF;
        s = eiu[j] + N_USER;
        d = eiu[E_HALF + j];
    } else return;
    int pos = atomicAdd(&g_cursor[d], 1);
    g_col[pos] = s;
}

// ------------------------- HMMA GEMM (R12/R14 config) -------------------------
template <int K, bool BIAS, typename AT, bool DUAL>
__global__ __launch_bounds__(256, 2) void gemm_mma(
    const AT* __restrict__ A0, const AT* __restrict__ A1,
    const __half* __restrict__ W0, const __half* __restrict__ W1p,
    const float* __restrict__ bias, __half* __restrict__ C, int M, int nbh)
{
    constexpr int WSTRIDE = 272;
    constexpr int WBYTES  = 128 * WSTRIDE;
    constexpr int ASTRIDE = 80;
    constexpr int ABYTES  = 128 * ASTRIDE;
    constexpr int N32     = K / 32;

    extern __shared__ char smem[];
    char* sW = smem;
    char* sA = smem + WBYTES;

    const int tid = threadIdx.x, lane = tid & 31, wid = tid >> 5;
    const int m0 = (wid >> 2) * 64, n0 = (wid & 3) * 32;

    const int bx = blockIdx.x;
    const int item = DUAL ? (bx >= nbh ? 1 : 0) : 0;
    const AT* __restrict__ A = item ? A1 : A0;
    const __half* __restrict__ Wt = item ? W1p : W0;
    const int block_row = ((DUAL && item) ? bx - nbh : bx) * 128;
    __half* __restrict__ Cc = C + (item ? (size_t)N_USER * HID : 0);
    const float* bs = bias + (DUAL ? item * HID : 0);

    const uint32_t sW_u = smem_u32(sW);
    const uint32_t sA_u = smem_u32(sA);

    auto stage_w = [&](int kh) {
        const uint32_t* wp = (const uint32_t*)Wt;
        #pragma unroll 4
        for (int i = tid; i < 128 * 64; i += 256) {
            int n = i >> 6, kp = i & 63;
            *(uint32_t*)(sW + n * WSTRIDE + kp * 4) = wp[n * (K / 2) + kh * 64 + kp];
        }
    };

    float acc[4][4][4];
    #pragma unroll
    for (int a = 0; a < 4; a++)
        #pragma unroll
        for (int b = 0; b < 4; b++)
            #pragma unroll
            for (int c = 0; c < 4; c++) acc[a][b][c] = 0.f;

    const uint32_t aoff = (uint32_t)((lane & 15) * ASTRIDE + ((lane & 16) ? 16 : 0));
    const uint32_t woff = (uint32_t)((((lane & 16) ? 8 : 0) + (lane & 7)) * WSTRIDE +
                                     ((lane & 8) ? 16 : 0));

    float4 vf[4];

    auto load_tile = [&](int ck) {
        #pragma unroll
        for (int q = 0; q < 4; q++) {
            int j = tid + 256 * q;
            int r = j >> 3, p = j & 7;
            int gr = block_row + r;
            if (gr > M - 1) gr = M - 1;
            vf[q] = *(const float4*)((const float*)A + (size_t)gr * K + ck * 32 + p * 4);
        }
    };
    auto store_tile = [&](int db) {
        char* buf = sA + db * ABYTES;
        #pragma unroll
        for (int q = 0; q < 4; q++) {
            int j = tid + 256 * q;
            int r = j >> 3, p = j & 7;
            uint2 o;
            o.x = h2_as_u32(__floats2half2_rn(vf[q].x, vf[q].y));
            o.y = h2_as_u32(__floats2half2_rn(vf[q].z, vf[q].w));
            *(uint2*)(buf + r * ASTRIDE + p * 8) = o;
        }
    };
    auto cp_tile = [&](int ck, int db) {
        uint32_t base = sA_u + db * ABYTES;
        #pragma unroll
        for (int q = 0; q < 2; q++) {
            int j = tid + 256 * q;
            int r = j >> 2, p = j & 3;
            int gr = block_row + r;
            if (gr > M - 1) gr = M - 1;
            cp_async16(base + r * ASTRIDE + p * 16,
                       (const __half*)A + (size_t)gr * K + ck * 32 + p * 8);
        }
        cp_commit();
    };

    stage_w(0);
    if constexpr (sizeof(AT) == 2) {
        cp_tile(0, 0);
        cp_wait0();
    } else {
        load_tile(0);
        store_tile(0);
    }
    __syncthreads();

    for (int i = 0; i < N32; i++) {
        if (i + 1 < N32) {
            if constexpr (sizeof(AT) == 2) cp_tile(i + 1, (i + 1) & 1);
            else load_tile(i + 1);
        }

        const uint32_t abase = sA_u + (i & 1) * ABYTES;

        #pragma unroll
        for (int c2 = 0; c2 < 2; c2++) {
            const int kk = (i * 2 + c2) & 7;
            const uint32_t wk = (uint32_t)(n0 * WSTRIDE + kk * 32) + woff;

            uint32_t wh[4][2], af[4][4];
            #pragma unroll
            for (int nt2 = 0; nt2 < 2; nt2++) {
                uint32_t q0, q1, q2, q3;
                ldsm_x4(q0, q1, q2, q3, sW_u + wk + nt2 * 16 * WSTRIDE);
                wh[nt2 * 2 + 0][0] = q0; wh[nt2 * 2 + 0][1] = q1;
                wh[nt2 * 2 + 1][0] = q2; wh[nt2 * 2 + 1][1] = q3;
            }
            #pragma unroll
            for (int mt = 0; mt < 4; mt++)
                ldsm_x4(af[mt][0], af[mt][1], af[mt][2], af[mt][3],
                        abase + (uint32_t)((m0 + mt * 16) * ASTRIDE) + aoff + c2 * 32);

            #pragma unroll
            for (int mt = 0; mt < 4; mt++)
                #pragma unroll
                for (int nt = 0; nt < 4; nt++)
                    mma16816(acc[mt][nt], af[mt], wh[nt]);
        }

        if (i + 1 < N32) {
            if constexpr (sizeof(AT) == 2) cp_wait0();
            else store_tile((i + 1) & 1);
        }
        __syncthreads();

        if constexpr (K > 128) {
            if (i == N32 / 2 - 1) {
                stage_w(1);
                __syncthreads();
            }
        }
    }

    #pragma unroll
    for (int nt = 0; nt < 4; nt++) {
        int col = n0 + nt * 8 + 2 * (lane & 3);
        float b0 = 0.f, b1 = 0.f;
        if (BIAS) { b0 = bs[col]; b1 = bs[col + 1]; }
        #pragma unroll
        for (int mt = 0; mt < 4; mt++) {
            int row = block_row + m0 + mt * 16 + (lane >> 2);
            if (row < M)
                *(__half2*)(Cc + (size_t)row * 128 + col) =
                    __floats2half2_rn(acc[mt][nt][0] + b0, acc[mt][nt][1] + b1);
            if (row + 8 < M)
                *(__half2*)(Cc + (size_t)(row + 8) * 128 + col) =
                    __floats2half2_rn(acc[mt][nt][2] + b0, acc[mt][nt][3] + b1);
        }
    }
}

// ------------------------- aggregation (R14 form) -----------------------------
template <typename OUTT>
__global__ __launch_bounds__(256)
void aggregate(const __half* __restrict__ hw, OUTT* __restrict__ out,
               const float* __restrict__ bias, int relu) {
    int node = (blockIdx.x * blockDim.x + threadIdx.x) >> 5;
    int lane = threadIdx.x & 31;
    if (node >= NNODE) return;

    float dv = g_dinv[node];
    float ws = dv * dv;

    const __half2* self = (const __half2*)(hw + (size_t)node * HID) + lane * 2;
    float2 s0 = __half22float2(self[0]);
    float2 s1 = __half22float2(self[1]);
    float4 acc = make_float4(s0.x * ws, s0.y * ws, s1.x * ws, s1.y * ws);
    float4 acc2 = make_float4(0.f, 0.f, 0.f, 0.f);

    int e = g_rowptr[node];
    const int end = g_rowptr[node + 1];

    for (; e + 3 < end; e += 4) {
        int c0 = g_col[e], c1 = g_col[e + 1], c2 = g_col[e + 2], c3 = g_col[e + 3];
        float w0 = g_dinv[c0] * dv;
        float w1 = g_dinv[c1] * dv;
        float w2 = g_dinv[c2] * dv;
        float w3 = g_dinv[c3] * dv;
        const __half2* u0 = (const __half2*)(hw + (size_t)c0 * HID) + lane * 2;
        const __half2* u1 = (const __half2*)(hw + (size_t)c1 * HID) + lane * 2;
        const __half2* u2 = (const __half2*)(hw + (size_t)c2 * HID) + lane * 2;
        const __half2* u3 = (const __half2*)(hw + (size_t)c3 * HID) + lane * 2;
        __half2 r0a = u0[0], r0b = u0[1];
        __half2 r1a = u1[0], r1b = u1[1];
        __half2 r2a = u2[0], r2b = u2[1];
        __half2 r3a = u3[0], r3b = u3[1];
        float2 a0 = __half22float2(r0a), a1 = __half22float2(r0b);
        float2 b0 = __half22float2(r1a), b1 = __half22float2(r1b);
        float2 d0 = __half22float2(r2a), d1 = __half22float2(r2b);
        float2 f0 = __half22float2(r3a), f1 = __half22float2(r3b);
        acc.x  = fmaf(w0, a0.x, acc.x);  acc.y  = fmaf(w0, a0.y, acc.y);
        acc.z  = fmaf(w0, a1.x, acc.z);  acc.w  = fmaf(w0, a1.y, acc.w);
        acc2.x = fmaf(w1, b0.x, acc2.x); acc2.y = fmaf(w1, b0.y, acc2.y);
        acc2.z = fmaf(w1, b1.x, acc2.z); acc2.w = fmaf(w1, b1.y, acc2.w);
        acc.x  = fmaf(w2, d0.x, acc.x);  acc.y  = fmaf(w2, d0.y, acc.y);
        acc.z  = fmaf(w2, d1.x, acc.z);  acc.w  = fmaf(w2, d1.y, acc.w);
        acc2.x = fmaf(w3, f0.x, acc2.x); acc2.y = fmaf(w3, f0.y, acc2.y);
        acc2.z = fmaf(w3, f1.x, acc2.z); acc2.w = fmaf(w3, f1.y, acc2.w);
    }
    for (; e < end; e++) {
        int c0 = g_col[e];
        float w0 = g_dinv[c0] * dv;
        const __half2* u0 = (const __half2*)(hw + (size_t)c0 * HID) + lane * 2;
        float2 a0 = __half22float2(u0[0]), a1 = __half22float2(u0[1]);
        acc.x = fmaf(w0, a0.x, acc.x); acc.y = fmaf(w0, a0.y, acc.y);
        acc.z = fmaf(w0, a1.x, acc.z); acc.w = fmaf(w0, a1.y, acc.w);
    }
    acc.x += acc2.x; acc.y += acc2.y; acc.z += acc2.z; acc.w += acc2.w;

    float4 b = ((const float4*)bias)[lane];
    acc.x += b.x; acc.y += b.y; acc.z += b.z; acc.w += b.w;
    if (relu) {
        acc.x = fmaxf(acc.x, 0.f); acc.y = fmaxf(acc.y, 0.f);
        acc.z = fmaxf(acc.z, 0.f); acc.w = fmaxf(acc.w, 0.f);
    }
    if constexpr (sizeof(OUTT) == 4) {
        ((float4*)((float*)out + (size_t)node * HID))[lane] = acc;
    } else {
        __half2* op = (__half2*)((__half*)out + (size_t)node * HID) + lane * 2;
        op[0] = __floats2half2_rn(acc.x, acc.y);
        op[1] = __floats2half2_rn(acc.z, acc.w);
    }
}

// ------------------------- driver --------------------------------------------
extern "C" void kernel_launch(void* const* d_in, const int* in_sizes, int n_in,
                              void* d_out, int out_size) {
    const float* x_user    = (const float*)d_in[0];
    const float* x_item    = (const float*)d_in[1];
    const int*   edge_ui   = (const int*)d_in[2];
    const int*   edge_iu   = (const int*)d_in[3];
    const float* W_in_user = (const float*)d_in[4];
    const float* b_in_user = (const float*)d_in[5];
    const float* W_in_item = (const float*)d_in[6];
    const float* b_in_item = (const float*)d_in[7];
    const float* W1        = (const float*)d_in[8];
    const float* b1        = (const float*)d_in[9];
    const float* W2        = (const float*)d_in[10];
    const float* b2        = (const float*)d_in[11];
    float* out = (float*)d_out;

    __half* hw16; __half* h16;
    __half* wt;
    float* bfold;
    cudaGetSymbolAddress((void**)&hw16,  g_hw16);
    cudaGetSymbolAddress((void**)&h16,   g_h16);
    cudaGetSymbolAddress((void**)&wt,    g_wt);
    cudaGetSymbolAddress((void**)&bfold, g_bfold);

    const int SMEM_GEMM = 34816 + 2 * 10240;   // 55296
    cudaFuncSetAttribute((const void*)gemm_mma<256, true, float, true>,
                         cudaFuncAttributeMaxDynamicSharedMemorySize, SMEM_GEMM);
    cudaFuncSetAttribute((const void*)gemm_mma<128, false, __half, false>,
                         cudaFuncAttributeMaxDynamicSharedMemorySize, SMEM_GEMM);

    const int NB_SCAN = (NNODE + 1023) / 1024;  // 196
    const int NB_ZERO = (NNODE + 255) / 256;    // 782
    const int NBU = (N_USER + 127) / 128;       // 782
    const int NB2 = (NNODE + 127) / 128;        // 1563

    // fork a side stream for the CSR chain (created per call; intentionally
    // never destroyed so capture never sees a destroyed resource)
    cudaStream_t s2;
    cudaStreamCreateWithFlags(&s2, cudaStreamNonBlocking);
    cudaEvent_t e0, e1;
    cudaEventCreateWithFlags(&e0, cudaEventDisableTiming);
    cudaEventCreateWithFlags(&e1, cudaEventDisableTiming);

    cudaEventRecord(e0, 0);
    cudaStreamWaitEvent(s2, e0, 0);

    // ---- branch B (s2): CSR chain ----
    zero_deg<<<NB_ZERO, 256, 0, s2>>>();
    build_deg<<<(E_TOT + 255) / 256, 256, 0, s2>>>(edge_ui, edge_iu);
    scan1<<<NB_SCAN, 1024, 0, s2>>>();
    scan2k<<<1, 256, 0, s2>>>();
    scan3<<<NB_SCAN, 1024, 0, s2>>>();
    fill_csr<<<(E_TOT + 255) / 256, 256, 0, s2>>>(edge_ui, edge_iu);
    cudaEventRecord(e1, s2);

    // ---- branch A (stream 0): weight prep + proj GEMM ----
    prep_weights<<<352, 256>>>(W_in_user, W_in_item, W1, W2, b_in_user, b_in_item);
    gemm_mma<256, true, float, true><<<2 * NBU, 256, SMEM_GEMM>>>(
        x_user, x_item, wt + WT_WU, wt + WT_WI, bfold, hw16, N_USER, NBU);

    // ---- join ----
    cudaStreamWaitEvent(0, e1, 0);

    // layer-1 aggregate -> h16 (fp16, relu)
    aggregate<__half><<<(NNODE * 32 + 255) / 256, 256>>>(hw16, h16, b1, 1);
    // layer-2 GEMM (fp16 A via cp.async)
    gemm_mma<128, false, __half, false><<<NB2, 256, SMEM_GEMM>>>(
        h16, h16, wt + WT_W2, wt + WT_W2, b2, hw16, NNODE, NB2);
    // layer-2 aggregate -> out (fp32)
    aggregate<float><<<(NNODE * 32 + 255) / 256, 256>>>(hw16, out, b2, 0);
}